// round 1
// baseline (speedup 1.0000x reference)
#include <cuda_runtime.h>
#include <cstdint>

#define HRR   1024
#define NDEC  16
#define OUTW  (HRR * (2 + 2 * NDEC))   // 34816 floats per row

// Precomputed decoder spectra: G[d][k] = conj(FFT(decoder_d))[k] / 1024
__device__ float2 g_G[NDEC * HRR];

static __device__ __forceinline__ float2 cmul(float2 a, float2 b) {
    return make_float2(fmaf(a.x, b.x, -a.y * b.y), fmaf(a.x, b.y, a.y * b.x));
}

// cos/sin(2*pi*t/32), t = 0..15
__device__ constexpr float C32T[16] = {
    1.0f,          0.980785280f,  0.923879533f,  0.831469612f,
    0.707106781f,  0.555570233f,  0.382683432f,  0.195090322f,
    0.0f,         -0.195090322f, -0.382683432f, -0.555570233f,
   -0.707106781f, -0.831469612f, -0.923879533f, -0.980785280f };
__device__ constexpr float S32T[16] = {
    0.0f,          0.195090322f,  0.382683432f,  0.555570233f,
    0.707106781f,  0.831469612f,  0.923879533f,  0.980785280f,
    1.0f,          0.980785280f,  0.923879533f,  0.831469612f,
    0.707106781f,  0.555570233f,  0.382683432f,  0.195090322f };

__device__ __host__ constexpr int brev5(int x) {
    return ((x & 1) << 4) | ((x & 2) << 2) | (x & 4) | ((x & 8) >> 2) | ((x & 16) >> 4);
}

// One DIF radix-2 stage of an in-register 32-point FFT.
// SGN = -1: forward (e^{-2pi i}); SGN = +1: inverse kernel (no 1/N).
template<int SGN, int M>
static __device__ __forceinline__ void fft32_stage(float2 v[32]) {
    constexpr int H = M / 2;
    constexpr int TS = 32 / M;
#pragma unroll
    for (int g = 0; g < 32; g += M) {
#pragma unroll
        for (int j = 0; j < H; j++) {
            const int t = j * TS;           // twiddle exponent, 0..15
            float2 a = v[g + j], b = v[g + j + H];
            v[g + j] = make_float2(a.x + b.x, a.y + b.y);
            float2 d = make_float2(a.x - b.x, a.y - b.y);
            if (t == 0) {
                v[g + j + H] = d;
            } else if (t == 8) {            // w = (0, SGN)
                v[g + j + H] = (SGN < 0) ? make_float2(d.y, -d.x)
                                         : make_float2(-d.y, d.x);
            } else {
                float2 w = make_float2(C32T[t], (SGN < 0) ? -S32T[t] : S32T[t]);
                v[g + j + H] = cmul(d, w);
            }
        }
    }
}

template<int SGN>
static __device__ __forceinline__ void fft32(float2 v[32]) {
    fft32_stage<SGN, 32>(v);
    fft32_stage<SGN, 16>(v);
    fft32_stage<SGN, 8>(v);
    fft32_stage<SGN, 4>(v);
    fft32_stage<SGN, 2>(v);
}

// Warp-level 1024-point complex FFT (four-step, 32 lanes x 32 regs).
// Input:  v[a] on lane b = x[32*a + b]   (natural order)
// Output: v[r] on lane c = X[c + 32*brev5(r)]
// tb: this warp's private 32*33 float2 transpose buffer in shared memory.
template<int SGN>
static __device__ __forceinline__ void warp_fft1024(float2 (&v)[32], int lane, float2* tb) {
    fft32<SGN>(v);   // per-lane FFT over a -> index c (bit-reversed in regs)

    // twiddle W_1024^{SGN * lane * c}, generated incrementally, + transpose store
    float ang = (float)SGN * (6.283185307179586f / 1024.0f) * (float)lane;
    float sn, cs;
    __sincosf(ang, &sn, &cs);
    float2 w = make_float2(cs, sn);
    float2 t = make_float2(1.0f, 0.0f);
#pragma unroll
    for (int c = 0; c < 32; c++) {
        tb[lane * 33 + c] = cmul(v[brev5(c)], t);   // natural-c layout, row = b
        t = cmul(t, w);
    }
    __syncwarp();
#pragma unroll
    for (int b = 0; b < 32; b++) v[b] = tb[b * 33 + lane];  // lane now holds fixed c
    __syncwarp();   // protect tb before caller's next use

    fft32<SGN>(v);   // FFT over b -> index d (bit-reversed in regs)
}

// ---------------------------------------------------------------------------
// Kernel 1: decoder spectra. One block (1 warp) per decoder.
__global__ __launch_bounds__(32)
void hrr_prep_kernel(const float* __restrict__ dec) {
    __shared__ float2 tb[32 * 33];
    const int lane = threadIdx.x;
    const int d = blockIdx.x;
    float2 v[32];
#pragma unroll
    for (int a = 0; a < 32; a++)
        v[a] = make_float2(__ldg(&dec[d * HRR + 32 * a + lane]), 0.0f);
    warp_fft1024<-1>(v, lane, tb);
    const float inv = 1.0f / 1024.0f;
#pragma unroll
    for (int r = 0; r < 32; r++) {
        int k = lane + 32 * brev5(r);
        g_G[d * HRR + k] = make_float2(v[r].x * inv, -v[r].y * inv);  // conj / N
    }
}

// ---------------------------------------------------------------------------
// Kernel 2: one CTA (4 warps) per batch row.
//   z = p + i*l; Z = FFT(z); for each decoder d: y = IFFT(G_d * Z);
//   Re(y) -> assoc_p[d], Im(y) -> assoc_l[d].
__global__ __launch_bounds__(128, 3)
void hrr_main_kernel(const float* __restrict__ P,
                     const float* __restrict__ L,
                     float* __restrict__ out) {
    __shared__ float2 zbuf[HRR];
    __shared__ float2 tb[4][32 * 33];

    const int b    = blockIdx.x;
    const int tid  = threadIdx.x;
    const int wid  = tid >> 5;
    const int lane = tid & 31;

    const float* pr = P + (size_t)b * HRR;
    const float* lr = L + (size_t)b * HRR;
    float* outr = out + (size_t)b * OUTW;

    // Copy p, l rows into out[0:2048) (vectorized, streaming stores)
    for (int i = tid; i < HRR / 4; i += 128) {
        float4 vp = __ldg((const float4*)pr + i);
        float4 vl = __ldg((const float4*)lr + i);
        __stcs((float4*)outr + i, vp);
        __stcs((float4*)(outr + HRR) + i, vl);
    }

    float2 v[32];

    // Forward FFT of z = p + i*l (warp 0), result shared via zbuf (natural k order)
    if (wid == 0) {
#pragma unroll
        for (int a = 0; a < 32; a++)
            v[a] = make_float2(__ldg(&pr[32 * a + lane]), __ldg(&lr[32 * a + lane]));
        warp_fft1024<-1>(v, lane, tb[0]);
#pragma unroll
        for (int r = 0; r < 32; r++)
            zbuf[lane + 32 * brev5(r)] = v[r];
    }
    __syncthreads();

    // 16 inverse FFTs, 4 per warp
    for (int d = wid; d < NDEC; d += 4) {
        const float2* G = g_G + d * HRR;
#pragma unroll
        for (int a = 0; a < 32; a++) {
            float2 z = zbuf[32 * a + lane];
            float2 g = __ldg(&G[32 * a + lane]);
            v[a] = cmul(z, g);
        }
        warp_fft1024<1>(v, lane, tb[wid]);

        float* op = outr + 2 * HRR + d * HRR;                // assoc_p block
        float* ol = outr + 2 * HRR + NDEC * HRR + d * HRR;   // assoc_l block
#pragma unroll
        for (int r = 0; r < 32; r++) {
            int k = lane + 32 * brev5(r);
            __stcs(&op[k], v[r].x);
            __stcs(&ol[k], v[r].y);
        }
    }
}

// ---------------------------------------------------------------------------
extern "C" void kernel_launch(void* const* d_in, const int* in_sizes, int n_in,
                              void* d_out, int out_size) {
    // metadata order: problemhrr [B,1024], lemmahrr [B,1024], decoders [16,1024]
    const float* P = (const float*)d_in[0];
    const float* L = (const float*)d_in[1];
    const float* D = (const float*)d_in[2];
    // defensive: identify the decoders tensor by its unique size
    if (in_sizes[0] == NDEC * HRR) {
        D = (const float*)d_in[0]; P = (const float*)d_in[1]; L = (const float*)d_in[2];
    } else if (in_sizes[1] == NDEC * HRR) {
        P = (const float*)d_in[0]; D = (const float*)d_in[1]; L = (const float*)d_in[2];
    }
    const int B = out_size / OUTW;

    hrr_prep_kernel<<<NDEC, 32>>>(D);
    hrr_main_kernel<<<B, 128>>>(P, L, (float*)d_out);
}